// round 4
// baseline (speedup 1.0000x reference)
#include <cuda_runtime.h>

// Problem constants (fixed by the dataset)
#define Bn   2
#define NP   2000
#define NN   2048
#define NREL 8192
#define NFD  128

// ---------------------------------------------------------------------------
// Device scratch (allocation-free: __device__ globals)
// Host obtains addresses via cudaGetSymbolAddress (capture-safe symbol lookup).
// ---------------------------------------------------------------------------
__device__ int   d_rr[Bn * NREL];
__device__ int   d_rs[Bn * NREL];
__device__ float d_pinp[Bn * NN * 19];
__device__ float d_relinp[Bn * NREL * 56];
__device__ float d_pe[Bn * NN * NFD];      // particle_encode
__device__ float d_re[Bn * NREL * NFD];    // relation_encode
__device__ float d_peff[Bn * NN * NFD];    // particle_effect
__device__ float d_s1[Bn * NREL * NFD];    // scratch A
__device__ float d_s2[Bn * NREL * NFD];    // scratch B / effect_rel
__device__ float d_agg[Bn * NN * NFD];     // scatter-add target / small scratch

// ---------------------------------------------------------------------------
// Index extraction from dense one-hot Rr/Rs (HBM-bound, single pass, float4)
// ---------------------------------------------------------------------------
__global__ void extract_idx_k(const float4* __restrict__ Rr4, const float4* __restrict__ Rs4) {
    const int n4 = Bn * NREL * NN / 4;  // 8,388,608
    const int stride = blockDim.x * gridDim.x;
    for (int i = blockIdx.x * blockDim.x + threadIdx.x; i < n4; i += stride) {
        float4 a = Rr4[i];
        if (a.x != 0.f || a.y != 0.f || a.z != 0.f || a.w != 0.f) {
            int base = i << 2;
            int row = base >> 11;     // /2048 (N = 2048 columns per relation row)
            int col = base & 2047;
            if (a.x != 0.f) d_rr[row] = col;
            if (a.y != 0.f) d_rr[row] = col + 1;
            if (a.z != 0.f) d_rr[row] = col + 2;
            if (a.w != 0.f) d_rr[row] = col + 3;
        }
        float4 s = Rs4[i];
        if (s.x != 0.f || s.y != 0.f || s.z != 0.f || s.w != 0.f) {
            int base = i << 2;
            int row = base >> 11;
            int col = base & 2047;
            if (s.x != 0.f) d_rs[row] = col;
            if (s.y != 0.f) d_rs[row] = col + 1;
            if (s.z != 0.f) d_rs[row] = col + 2;
            if (s.w != 0.f) d_rs[row] = col + 3;
        }
    }
}

// ---------------------------------------------------------------------------
// Build p_inputs [B,N,19] = attrs(2) | state_norm(12) | phys(1) | action(3) | den(1)
// ---------------------------------------------------------------------------
__global__ void build_pinp_k(const float* __restrict__ state, const float* __restrict__ attrs,
                             const float* __restrict__ action, const float* __restrict__ pden,
                             const float* __restrict__ phys) {
    int i = blockIdx.x * blockDim.x + threadIdx.x;
    if (i >= Bn * NN) return;
    int b = i >> 11, n = i & 2047;
    float* o = d_pinp + i * 19;
    o[0] = attrs[i * 2 + 0];
    o[1] = attrs[i * 2 + 1];
    const float* st = state + (size_t)(b * 4) * NN * 3 + (size_t)n * 3;
    const int HS = NN * 3;
    float s0[3], s1[3], s2[3], s3[3];
#pragma unroll
    for (int c = 0; c < 3; c++) {
        s0[c] = st[c];
        s1[c] = st[HS + c];
        s2[c] = st[2 * HS + c];
        s3[c] = st[3 * HS + c];
    }
#pragma unroll
    for (int c = 0; c < 3; c++) {
        o[2 + c]  = s1[c] - s0[c];
        o[5 + c]  = s2[c] - s1[c];
        o[8 + c]  = s3[c] - s2[c];
        o[11 + c] = s3[c];
    }
    o[14] = (n < NP) ? phys[b] : 0.f;
#pragma unroll
    for (int c = 0; c < 3; c++) o[15 + c] = action[i * 3 + c];
    o[18] = (n < NP) ? pden[b] : 0.f;
}

// ---------------------------------------------------------------------------
// Build rel_inputs [B,n_rel,56] = p_r(19)|p_s(19)|a_r(2)|a_s(2)|grp(1)|posdiff(12)|dendiff(1)
// ---------------------------------------------------------------------------
__global__ void build_relinp_k(const float* __restrict__ attrs, const float* __restrict__ pinst) {
    int i = blockIdx.x * blockDim.x + threadIdx.x;
    if (i >= Bn * NREL) return;
    int b = i >> 13;
    int nr = d_rr[i], ns = d_rs[i];
    const float* pr = d_pinp + ((b << 11) + nr) * 19;
    const float* ps = d_pinp + ((b << 11) + ns) * 19;
    float* o = d_relinp + i * 56;
#pragma unroll
    for (int c = 0; c < 19; c++) { o[c] = pr[c]; o[19 + c] = ps[c]; }
    o[38] = attrs[((b << 11) + nr) * 2 + 0];
    o[39] = attrs[((b << 11) + nr) * 2 + 1];
    o[40] = attrs[((b << 11) + ns) * 2 + 0];
    o[41] = attrs[((b << 11) + ns) * 2 + 1];
    float gd = 0.f;
    bool ri = nr < NP, si = ns < NP;
    if (ri && si) {
        const float* gr = pinst + (b * NP + nr) * 8;
        const float* gs = pinst + (b * NP + ns) * 8;
#pragma unroll
        for (int j = 0; j < 8; j++) gd += fabsf(gr[j] - gs[j]);
    } else if (ri || si) {
        const float* g1 = pinst + (b * NP + (ri ? nr : ns)) * 8;
#pragma unroll
        for (int j = 0; j < 8; j++) gd += fabsf(g1[j]);
    }
    o[42] = gd;
#pragma unroll
    for (int c = 0; c < 12; c++) o[43 + c] = pr[2 + c] - ps[2 + c];
    o[55] = pr[18] - ps[18];
}

// ---------------------------------------------------------------------------
// Generic fused MLP layer: out[M,128] = act(A[M,K] @ W[K,128] + bias (+resid))
// Block: 128 threads (one output column each), TMv rows per block. sA reads
// in the inner loop are warp-broadcasts, sW reads conflict-free, so the inner
// loop is FFMA-pipe-bound (~76% FFMA fraction at TMv=16).
// ---------------------------------------------------------------------------
constexpr int BK = 32;

template <int TMv, int K, bool RELU, bool RESID, class Loader>
__device__ __forceinline__ void mlp_body(Loader ld, const float* __restrict__ W,
                                         const float* __restrict__ bias,
                                         float* __restrict__ out,
                                         const float* __restrict__ resid) {
    __shared__ float sA[TMv * BK];
    __shared__ float sW[BK * 128];
    const int t = threadIdx.x;
    const int row0 = blockIdx.x * TMv;
    float acc[TMv];
    const float bv = bias[t];
#pragma unroll
    for (int r = 0; r < TMv; r++) acc[r] = bv;

#pragma unroll 1
    for (int k0 = 0; k0 < K; k0 += BK) {
        const int kc = (K - k0 < BK) ? (K - k0) : BK;
        __syncthreads();
#pragma unroll 1
        for (int i = t; i < TMv * BK; i += 128) {
            const int r = i / BK, k = i % BK;
            sA[i] = (k < kc) ? ld(row0 + r, k0 + k) : 0.f;
        }
#pragma unroll 1
        for (int i = 0; i < BK; i++) {
            sW[i * 128 + t] = (i < kc) ? W[(k0 + i) * 128 + t] : 0.f;
        }
        __syncthreads();
        for (int kk = 0; kk < BK; kk += 4) {
            const float w0 = sW[(kk + 0) * 128 + t];
            const float w1 = sW[(kk + 1) * 128 + t];
            const float w2 = sW[(kk + 2) * 128 + t];
            const float w3 = sW[(kk + 3) * 128 + t];
#pragma unroll
            for (int r = 0; r < TMv; r++) {
                const float4 a = *reinterpret_cast<const float4*>(&sA[r * BK + kk]);
                acc[r] = fmaf(a.x, w0, acc[r]);
                acc[r] = fmaf(a.y, w1, acc[r]);
                acc[r] = fmaf(a.z, w2, acc[r]);
                acc[r] = fmaf(a.w, w3, acc[r]);
            }
        }
    }
#pragma unroll
    for (int r = 0; r < TMv; r++) {
        float v = acc[r];
        if (RESID) v += resid[(row0 + r) * 128 + t];
        if (RELU) v = fmaxf(v, 0.f);
        out[(row0 + r) * 128 + t] = v;
    }
}

struct PlainLd {
    const float* A; int Kd;
    __device__ __forceinline__ float operator()(int row, int k) const { return A[row * Kd + k]; }
};
struct Gather3Ld {  // [relation_encode | eff[rr] | eff[rs]]  K=384
    const float* re; const float* eff;
    __device__ __forceinline__ float operator()(int row, int k) const {
        if (k < 128) return re[row * 128 + k];
        const int b = row >> 13;
        if (k < 256) return eff[((b << 11) + d_rr[row]) * 128 + (k - 128)];
        return eff[((b << 11) + d_rs[row]) * 128 + (k - 256)];
    }
};
struct Gather2Ld {  // [particle_encode | agg]  K=256
    const float* pe; const float* agg;
    __device__ __forceinline__ float operator()(int row, int k) const {
        return (k < 128) ? pe[row * 128 + k] : agg[row * 128 + (k - 128)];
    }
};

template <int TMv, int K, bool RELU>
__global__ void __launch_bounds__(128) linear_k(const float* __restrict__ A,
                                                const float* __restrict__ W,
                                                const float* __restrict__ bias,
                                                float* __restrict__ out) {
    mlp_body<TMv, K, RELU, false>(PlainLd{A, K}, W, bias, out, nullptr);
}

__global__ void __launch_bounds__(128) relprop_k(const float* __restrict__ eff,
                                                 const float* __restrict__ W,
                                                 const float* __restrict__ bias) {
    // d_re / d_s2 referenced directly in device code (valid decay here)
    mlp_body<16, 384, true, false>(Gather3Ld{d_re, eff}, W, bias, d_s2, nullptr);
}

__global__ void __launch_bounds__(128) partprop_k(const float* __restrict__ resid,
                                                  const float* __restrict__ W,
                                                  const float* __restrict__ bias) {
    mlp_body<8, 256, true, true>(Gather2Ld{d_pe, d_agg}, W, bias, d_peff, resid);
}

// ---------------------------------------------------------------------------
// Scatter-add: agg[b, rr[r], :] += effect_rel[r, :]
// ---------------------------------------------------------------------------
__global__ void zero_agg_k() {
    int i = blockIdx.x * blockDim.x + threadIdx.x;
    if (i < Bn * NN * NFD) d_agg[i] = 0.f;
}

__global__ void scatter_k() {
    int i = blockIdx.x * blockDim.x + threadIdx.x;  // Bn*NREL*128
    int rg = i >> 7, dcol = i & 127;
    int b = rg >> 13;
    int n = d_rr[rg];
    atomicAdd(&d_agg[((b << 11) + n) * 128 + dcol], d_s2[i]);
}

// ---------------------------------------------------------------------------
// Final predictor head: motion = h @ W2[128,3] + b2, clip, add last state
// ---------------------------------------------------------------------------
__global__ void final_k(const float* __restrict__ state, const float* __restrict__ W2,
                        const float* __restrict__ b2, float* __restrict__ out) {
    int i = blockIdx.x * blockDim.x + threadIdx.x;
    if (i >= Bn * NP * 3) return;
    int j = i % 3;
    int p = (i / 3) % NP;
    int b = i / (NP * 3);
    const float* h = d_s1 + ((b << 11) + p) * 128;
    float acc = b2[j];
#pragma unroll 4
    for (int k = 0; k < 128; k++) acc = fmaf(h[k], W2[k * 3 + j], acc);
    acc = fminf(fmaxf(acc, -100.f), 100.f);
    out[i] = state[((size_t)(b * 4 + 3) * NN + p) * 3 + j] + acc;
}

// ---------------------------------------------------------------------------
// Host launch. cudaGetSymbolAddress is a symbol lookup (no allocation, no
// stream op) — safe under graph capture and the _HX_ENFORCE guards.
// ---------------------------------------------------------------------------
static float* symaddr(const void* s) {
    void* p = nullptr;
    cudaGetSymbolAddress(&p, s);
    return (float*)p;
}

extern "C" void kernel_launch(void* const* d_in, const int* in_sizes, int n_in,
                              void* d_out, int out_size) {
    const float* state = (const float*)d_in[0];
    const float* attrs = (const float*)d_in[1];
    const float* Rr    = (const float*)d_in[2];
    const float* Rs    = (const float*)d_in[3];
    const float* pinst = (const float*)d_in[4];
    const float* action = (const float*)d_in[5];
    const float* pden  = (const float*)d_in[6];
    const float* phys  = (const float*)d_in[7];
    const float* peW0 = (const float*)d_in[8],  *peb0 = (const float*)d_in[9];
    const float* peW1 = (const float*)d_in[10], *peb1 = (const float*)d_in[11];
    const float* peW2 = (const float*)d_in[12], *peb2 = (const float*)d_in[13];
    const float* reW0 = (const float*)d_in[14], *reb0 = (const float*)d_in[15];
    const float* reW1 = (const float*)d_in[16], *reb1 = (const float*)d_in[17];
    const float* reW2 = (const float*)d_in[18], *reb2 = (const float*)d_in[19];
    const float* ppW  = (const float*)d_in[20], *ppb  = (const float*)d_in[21];
    const float* rpW  = (const float*)d_in[22], *rpb  = (const float*)d_in[23];
    const float* npW0 = (const float*)d_in[24], *npb0 = (const float*)d_in[25];
    const float* npW1 = (const float*)d_in[26], *npb1 = (const float*)d_in[27];
    const float* npW2 = (const float*)d_in[28], *npb2 = (const float*)d_in[29];
    float* out = (float*)d_out;

    float* pinp = symaddr(d_pinp);
    float* reli = symaddr(d_relinp);
    float* pe   = symaddr(d_pe);
    float* re   = symaddr(d_re);
    float* peff = symaddr(d_peff);
    float* s1   = symaddr(d_s1);
    float* s2   = symaddr(d_s2);
    float* agg  = symaddr(d_agg);

    // 1. indices from one-hot (HBM-bound single pass over 268 MB)
    extract_idx_k<<<8192, 256>>>((const float4*)Rr, (const float4*)Rs);

    // 2. node features
    build_pinp_k<<<(Bn * NN + 127) / 128, 128>>>(state, attrs, action, pden, phys);

    // 3. particle encoder: 19 -> 128 -> 128 -> 128    (M = 4096, TM = 8)
    linear_k<8, 19, true><<<Bn * NN / 8, 128>>>(pinp, peW0, peb0, agg);
    linear_k<8, 128, true><<<Bn * NN / 8, 128>>>(agg, peW1, peb1, s1);
    linear_k<8, 128, true><<<Bn * NN / 8, 128>>>(s1, peW2, peb2, pe);

    // 4. edge features + relation encoder: 56 -> 128 -> 128 -> 128  (M = 16384, TM = 16)
    build_relinp_k<<<(Bn * NREL + 127) / 128, 128>>>(attrs, pinst);
    linear_k<16, 56, true><<<Bn * NREL / 16, 128>>>(reli, reW0, reb0, s1);
    linear_k<16, 128, true><<<Bn * NREL / 16, 128>>>(s1, reW1, reb1, s2);
    linear_k<16, 128, true><<<Bn * NREL / 16, 128>>>(s2, reW2, reb2, re);

    // 5. 3 propagation steps
    for (int p = 0; p < 3; p++) {
        const float* src = (p == 0) ? pe : peff;
        relprop_k<<<Bn * NREL / 16, 128>>>(src, rpW, rpb);
        zero_agg_k<<<(Bn * NN * NFD) / 256, 256>>>();
        scatter_k<<<Bn * NREL, 128>>>();
        partprop_k<<<Bn * NN / 8, 128>>>(src, ppW, ppb);
    }

    // 6. motion head
    linear_k<8, 128, true><<<Bn * NN / 8, 128>>>(peff, npW0, npb0, agg);
    linear_k<8, 128, true><<<Bn * NN / 8, 128>>>(agg, npW1, npb1, s1);
    final_k<<<(Bn * NP * 3 + 127) / 128, 128>>>(state, npW2, npb2, out);
}

// round 5
// speedup vs baseline: 1.9239x; 1.9239x over previous
#include <cuda_runtime.h>

// Problem constants (fixed by the dataset)
#define Bn   2
#define NP   2000
#define NN   2048
#define NREL 8192
#define NFD  128

// ---------------------------------------------------------------------------
// Device scratch (allocation-free: __device__ globals)
// ---------------------------------------------------------------------------
__device__ int   d_rr[Bn * NREL];
__device__ int   d_rs[Bn * NREL];
__device__ float d_pinp[Bn * NN * 19];
__device__ float d_relinp[Bn * NREL * 56];
__device__ float d_pe[Bn * NN * NFD];      // particle_encode
__device__ float d_re[Bn * NREL * NFD];    // relation_encode
__device__ float d_peff[Bn * NN * NFD];    // particle_effect
__device__ float d_s1[Bn * NREL * NFD];    // scratch A
__device__ float d_s2[Bn * NREL * NFD];    // scratch B / effect_rel
__device__ float d_agg[Bn * NN * NFD];     // scatter-add target / small scratch

// ---------------------------------------------------------------------------
// Index extraction from dense one-hot Rr/Rs (HBM-bound, single pass, float4)
// ---------------------------------------------------------------------------
__global__ void extract_idx_k(const float4* __restrict__ Rr4, const float4* __restrict__ Rs4) {
    const int n4 = Bn * NREL * NN / 4;  // 8,388,608
    const int stride = blockDim.x * gridDim.x;
    for (int i = blockIdx.x * blockDim.x + threadIdx.x; i < n4; i += stride) {
        float4 a = Rr4[i];
        if (a.x != 0.f || a.y != 0.f || a.z != 0.f || a.w != 0.f) {
            int base = i << 2;
            int row = base >> 11;     // /2048
            int col = base & 2047;
            if (a.x != 0.f) d_rr[row] = col;
            if (a.y != 0.f) d_rr[row] = col + 1;
            if (a.z != 0.f) d_rr[row] = col + 2;
            if (a.w != 0.f) d_rr[row] = col + 3;
        }
        float4 s = Rs4[i];
        if (s.x != 0.f || s.y != 0.f || s.z != 0.f || s.w != 0.f) {
            int base = i << 2;
            int row = base >> 11;
            int col = base & 2047;
            if (s.x != 0.f) d_rs[row] = col;
            if (s.y != 0.f) d_rs[row] = col + 1;
            if (s.z != 0.f) d_rs[row] = col + 2;
            if (s.w != 0.f) d_rs[row] = col + 3;
        }
    }
}

// ---------------------------------------------------------------------------
// Build p_inputs [B,N,19] = attrs(2) | state_norm(12) | phys(1) | action(3) | den(1)
// ---------------------------------------------------------------------------
__global__ void build_pinp_k(const float* __restrict__ state, const float* __restrict__ attrs,
                             const float* __restrict__ action, const float* __restrict__ pden,
                             const float* __restrict__ phys) {
    int i = blockIdx.x * blockDim.x + threadIdx.x;
    if (i >= Bn * NN) return;
    int b = i >> 11, n = i & 2047;
    float* o = d_pinp + i * 19;
    o[0] = attrs[i * 2 + 0];
    o[1] = attrs[i * 2 + 1];
    const float* st = state + (size_t)(b * 4) * NN * 3 + (size_t)n * 3;
    const int HS = NN * 3;
    float s0[3], s1[3], s2[3], s3[3];
#pragma unroll
    for (int c = 0; c < 3; c++) {
        s0[c] = st[c];
        s1[c] = st[HS + c];
        s2[c] = st[2 * HS + c];
        s3[c] = st[3 * HS + c];
    }
#pragma unroll
    for (int c = 0; c < 3; c++) {
        o[2 + c]  = s1[c] - s0[c];
        o[5 + c]  = s2[c] - s1[c];
        o[8 + c]  = s3[c] - s2[c];
        o[11 + c] = s3[c];
    }
    o[14] = (n < NP) ? phys[b] : 0.f;
#pragma unroll
    for (int c = 0; c < 3; c++) o[15 + c] = action[i * 3 + c];
    o[18] = (n < NP) ? pden[b] : 0.f;
}

// ---------------------------------------------------------------------------
// Build rel_inputs [B,n_rel,56]
// ---------------------------------------------------------------------------
__global__ void build_relinp_k(const float* __restrict__ attrs, const float* __restrict__ pinst) {
    int i = blockIdx.x * blockDim.x + threadIdx.x;
    if (i >= Bn * NREL) return;
    int b = i >> 13;
    int nr = d_rr[i], ns = d_rs[i];
    const float* pr = d_pinp + ((b << 11) + nr) * 19;
    const float* ps = d_pinp + ((b << 11) + ns) * 19;
    float* o = d_relinp + i * 56;
#pragma unroll
    for (int c = 0; c < 19; c++) { o[c] = pr[c]; o[19 + c] = ps[c]; }
    o[38] = attrs[((b << 11) + nr) * 2 + 0];
    o[39] = attrs[((b << 11) + nr) * 2 + 1];
    o[40] = attrs[((b << 11) + ns) * 2 + 0];
    o[41] = attrs[((b << 11) + ns) * 2 + 1];
    float gd = 0.f;
    bool ri = nr < NP, si = ns < NP;
    if (ri && si) {
        const float* gr = pinst + (b * NP + nr) * 8;
        const float* gs = pinst + (b * NP + ns) * 8;
#pragma unroll
        for (int j = 0; j < 8; j++) gd += fabsf(gr[j] - gs[j]);
    } else if (ri || si) {
        const float* g1 = pinst + (b * NP + (ri ? nr : ns)) * 8;
#pragma unroll
        for (int j = 0; j < 8; j++) gd += fabsf(g1[j]);
    }
    o[42] = gd;
#pragma unroll
    for (int c = 0; c < 12; c++) o[43 + c] = pr[2 + c] - ps[2 + c];
    o[55] = pr[18] - ps[18];
}

// ---------------------------------------------------------------------------
// Fused MLP layer, 256-thread blocks.
//   out[M,128] = act(A[M,K] @ W[K,128] + bias (+resid))
// Thread (col = t&127, half = t>>7); each thread computes RPT = TMv/2 rows of
// one column. W staged per chunk via float4; A staged via Loader functor.
// Inner loop: w-reads conflict-free, a-reads warp-broadcast -> FFMA-bound.
// ---------------------------------------------------------------------------
constexpr int BK = 32;

template <int TMv, int K, bool RELU, bool RESID, class Loader>
__device__ __forceinline__ void mlp_body(Loader ld, const float* __restrict__ W,
                                         const float* __restrict__ bias,
                                         float* __restrict__ out,
                                         const float* __restrict__ resid) {
    constexpr int RPT = TMv / 2;                  // rows per thread
    __shared__ __align__(16) float sA[TMv * BK];
    __shared__ __align__(16) float sW[BK * 128];
    const int t = threadIdx.x;                    // 0..255
    const int col = t & 127;
    const int half = t >> 7;
    const int blockRow0 = blockIdx.x * TMv;
    const int myRow0 = half * RPT;

    float acc[RPT];
    const float bv = bias[col];
#pragma unroll
    for (int r = 0; r < RPT; r++) acc[r] = bv;

#pragma unroll 1
    for (int k0 = 0; k0 < K; k0 += BK) {
        const int kc = (K - k0 < BK) ? (K - k0) : BK;
        __syncthreads();
        // stage A tile: TMv*BK floats by 256 threads
#pragma unroll 1
        for (int i = t; i < TMv * BK; i += 256) {
            const int r = i / BK, k = i % BK;
            sA[i] = (k < kc) ? ld(blockRow0 + r, k0 + k) : 0.f;
        }
        // stage W tile as float4: BK rows x 32 float4 per row
#pragma unroll 1
        for (int i = t; i < BK * 32; i += 256) {
            const int k = i >> 5, c4 = i & 31;
            float4 v = make_float4(0.f, 0.f, 0.f, 0.f);
            if (k < kc) v = reinterpret_cast<const float4*>(W + (size_t)(k0 + k) * 128)[c4];
            reinterpret_cast<float4*>(sW)[i] = v;
        }
        __syncthreads();
#pragma unroll
        for (int kk = 0; kk < BK; kk += 4) {
            const float w0 = sW[(kk + 0) * 128 + col];
            const float w1 = sW[(kk + 1) * 128 + col];
            const float w2 = sW[(kk + 2) * 128 + col];
            const float w3 = sW[(kk + 3) * 128 + col];
#pragma unroll
            for (int r = 0; r < RPT; r++) {
                const float4 a = *reinterpret_cast<const float4*>(&sA[(myRow0 + r) * BK + kk]);
                acc[r] = fmaf(a.x, w0, acc[r]);
                acc[r] = fmaf(a.y, w1, acc[r]);
                acc[r] = fmaf(a.z, w2, acc[r]);
                acc[r] = fmaf(a.w, w3, acc[r]);
            }
        }
    }
#pragma unroll
    for (int r = 0; r < RPT; r++) {
        const int row = blockRow0 + myRow0 + r;
        float v = acc[r];
        if (RESID) v += resid[row * 128 + col];
        if (RELU) v = fmaxf(v, 0.f);
        out[row * 128 + col] = v;
    }
}

struct PlainLd {
    const float* A; int Kd;
    __device__ __forceinline__ float operator()(int row, int k) const { return A[row * Kd + k]; }
};
struct Gather3Ld {  // [relation_encode | eff[rr] | eff[rs]]  K=384
    const float* re; const float* eff;
    __device__ __forceinline__ float operator()(int row, int k) const {
        if (k < 128) return re[row * 128 + k];
        const int b = row >> 13;
        if (k < 256) return eff[((b << 11) + d_rr[row]) * 128 + (k - 128)];
        return eff[((b << 11) + d_rs[row]) * 128 + (k - 256)];
    }
};
struct Gather2Ld {  // [particle_encode | agg]  K=256
    const float* pe; const float* agg;
    __device__ __forceinline__ float operator()(int row, int k) const {
        return (k < 128) ? pe[row * 128 + k] : agg[row * 128 + (k - 128)];
    }
};

template <int TMv, int K, bool RELU>
__global__ void __launch_bounds__(256) linear_k(const float* __restrict__ A,
                                                const float* __restrict__ W,
                                                const float* __restrict__ bias,
                                                float* __restrict__ out) {
    mlp_body<TMv, K, RELU, false>(PlainLd{A, K}, W, bias, out, nullptr);
}

__global__ void __launch_bounds__(256) relprop_k(const float* __restrict__ eff,
                                                 const float* __restrict__ W,
                                                 const float* __restrict__ bias) {
    mlp_body<16, 384, true, false>(Gather3Ld{d_re, eff}, W, bias, d_s2, nullptr);
}

__global__ void __launch_bounds__(256) partprop_k(const float* __restrict__ resid,
                                                  const float* __restrict__ W,
                                                  const float* __restrict__ bias) {
    mlp_body<8, 256, true, true>(Gather2Ld{d_pe, d_agg}, W, bias, d_peff, resid);
}

// ---------------------------------------------------------------------------
// Scatter-add: agg[b, rr[r], :] += effect_rel[r, :]
// ---------------------------------------------------------------------------
__global__ void zero_agg_k() {
    int i = blockIdx.x * blockDim.x + threadIdx.x;
    if (i < Bn * NN * NFD) d_agg[i] = 0.f;
}

__global__ void scatter_k() {
    int i = blockIdx.x * blockDim.x + threadIdx.x;  // Bn*NREL*128
    int rg = i >> 7, dcol = i & 127;
    int b = rg >> 13;
    int n = d_rr[rg];
    atomicAdd(&d_agg[((b << 11) + n) * 128 + dcol], d_s2[i]);
}

// ---------------------------------------------------------------------------
// Final predictor head
// ---------------------------------------------------------------------------
__global__ void final_k(const float* __restrict__ state, const float* __restrict__ W2,
                        const float* __restrict__ b2, float* __restrict__ out) {
    int i = blockIdx.x * blockDim.x + threadIdx.x;
    if (i >= Bn * NP * 3) return;
    int j = i % 3;
    int p = (i / 3) % NP;
    int b = i / (NP * 3);
    const float* h = d_s1 + ((b << 11) + p) * 128;
    float acc = b2[j];
#pragma unroll 4
    for (int k = 0; k < 128; k++) acc = fmaf(h[k], W2[k * 3 + j], acc);
    acc = fminf(fmaxf(acc, -100.f), 100.f);
    out[i] = state[((size_t)(b * 4 + 3) * NN + p) * 3 + j] + acc;
}

// ---------------------------------------------------------------------------
// Host launch (kernel launches + capture-safe symbol lookups only)
// ---------------------------------------------------------------------------
static float* symaddr(const void* s) {
    void* p = nullptr;
    cudaGetSymbolAddress(&p, s);
    return (float*)p;
}

extern "C" void kernel_launch(void* const* d_in, const int* in_sizes, int n_in,
                              void* d_out, int out_size) {
    const float* state = (const float*)d_in[0];
    const float* attrs = (const float*)d_in[1];
    const float* Rr    = (const float*)d_in[2];
    const float* Rs    = (const float*)d_in[3];
    const float* pinst = (const float*)d_in[4];
    const float* action = (const float*)d_in[5];
    const float* pden  = (const float*)d_in[6];
    const float* phys  = (const float*)d_in[7];
    const float* peW0 = (const float*)d_in[8],  *peb0 = (const float*)d_in[9];
    const float* peW1 = (const float*)d_in[10], *peb1 = (const float*)d_in[11];
    const float* peW2 = (const float*)d_in[12], *peb2 = (const float*)d_in[13];
    const float* reW0 = (const float*)d_in[14], *reb0 = (const float*)d_in[15];
    const float* reW1 = (const float*)d_in[16], *reb1 = (const float*)d_in[17];
    const float* reW2 = (const float*)d_in[18], *reb2 = (const float*)d_in[19];
    const float* ppW  = (const float*)d_in[20], *ppb  = (const float*)d_in[21];
    const float* rpW  = (const float*)d_in[22], *rpb  = (const float*)d_in[23];
    const float* npW0 = (const float*)d_in[24], *npb0 = (const float*)d_in[25];
    const float* npW1 = (const float*)d_in[26], *npb1 = (const float*)d_in[27];
    const float* npW2 = (const float*)d_in[28], *npb2 = (const float*)d_in[29];
    float* out = (float*)d_out;

    float* pinp = symaddr(d_pinp);
    float* reli = symaddr(d_relinp);
    float* pe   = symaddr(d_pe);
    float* re   = symaddr(d_re);
    float* peff = symaddr(d_peff);
    float* s1   = symaddr(d_s1);
    float* s2   = symaddr(d_s2);
    float* agg  = symaddr(d_agg);

    // 1. indices from one-hot (HBM-bound single pass over 268 MB)
    extract_idx_k<<<8192, 256>>>((const float4*)Rr, (const float4*)Rs);

    // 2. node features
    build_pinp_k<<<(Bn * NN + 127) / 128, 128>>>(state, attrs, action, pden, phys);

    // 3. particle encoder: 19 -> 128 -> 128 -> 128    (M = 4096, TMv = 8, 512 blocks)
    linear_k<8, 19, true><<<Bn * NN / 8, 256>>>(pinp, peW0, peb0, agg);
    linear_k<8, 128, true><<<Bn * NN / 8, 256>>>(agg, peW1, peb1, s1);
    linear_k<8, 128, true><<<Bn * NN / 8, 256>>>(s1, peW2, peb2, pe);

    // 4. edge features + relation encoder: 56 -> 128 -> 128 -> 128  (M = 16384, TMv = 16)
    build_relinp_k<<<(Bn * NREL + 127) / 128, 128>>>(attrs, pinst);
    linear_k<16, 56, true><<<Bn * NREL / 16, 256>>>(reli, reW0, reb0, s1);
    linear_k<16, 128, true><<<Bn * NREL / 16, 256>>>(s1, reW1, reb1, s2);
    linear_k<16, 128, true><<<Bn * NREL / 16, 256>>>(s2, reW2, reb2, re);

    // 5. 3 propagation steps
    for (int p = 0; p < 3; p++) {
        const float* src = (p == 0) ? pe : peff;
        relprop_k<<<Bn * NREL / 16, 256>>>(src, rpW, rpb);
        zero_agg_k<<<(Bn * NN * NFD) / 256, 256>>>();
        scatter_k<<<Bn * NREL, 128>>>();
        partprop_k<<<Bn * NN / 8, 256>>>(src, ppW, ppb);
    }

    // 6. motion head
    linear_k<8, 128, true><<<Bn * NN / 8, 256>>>(peff, npW0, npb0, agg);
    linear_k<8, 128, true><<<Bn * NN / 8, 256>>>(agg, npW1, npb1, s1);
    final_k<<<(Bn * NP * 3 + 127) / 128, 128>>>(state, npW2, npb2, out);
}

// round 6
// speedup vs baseline: 2.0555x; 1.0684x over previous
#include <cuda_runtime.h>

// Problem constants (fixed by the dataset)
#define Bn   2
#define NP   2000
#define NN   2048
#define NREL 8192
#define NFD  128

typedef unsigned long long ull;

// ---------------------------------------------------------------------------
// Device scratch (allocation-free __device__ globals)
// ---------------------------------------------------------------------------
__device__ int   d_rr[Bn * NREL];
__device__ int   d_rs[Bn * NREL];
__device__ float d_pinp[Bn * NN * 19];
__device__ float d_relinp[Bn * NREL * 56];
__device__ float d_pe[Bn * NN * NFD];
__device__ float d_re[Bn * NREL * NFD];
__device__ float d_peff[Bn * NN * NFD];
__device__ float d_s1[Bn * NN * NFD];
__device__ float d_s2[Bn * NREL * NFD];
__device__ float d_agg[Bn * NN * NFD];

// ---------------------------------------------------------------------------
// f32x2 packed FMA (SASS FFMA2): d = a * b + d elementwise on packed fp32 pairs
// ---------------------------------------------------------------------------
__device__ __forceinline__ void fma2(ull& d, ull a, ull b) {
    asm("fma.rn.f32x2 %0, %1, %2, %0;" : "+l"(d) : "l"(a), "l"(b));
}
__device__ __forceinline__ float unpack_sum(ull v) {
    float2 f = *reinterpret_cast<float2*>(&v);
    return f.x + f.y;
}

// ---------------------------------------------------------------------------
// Index extraction from dense one-hot Rr/Rs (HBM-bound single pass)
// ---------------------------------------------------------------------------
__global__ void extract_idx_k(const float4* __restrict__ Rr4, const float4* __restrict__ Rs4) {
    const int n4 = Bn * NREL * NN / 4;
    const int stride = blockDim.x * gridDim.x;
    for (int i = blockIdx.x * blockDim.x + threadIdx.x; i < n4; i += stride) {
        float4 a = Rr4[i];
        if (a.x != 0.f || a.y != 0.f || a.z != 0.f || a.w != 0.f) {
            int base = i << 2, row = base >> 11, col = base & 2047;
            if (a.x != 0.f) d_rr[row] = col;
            if (a.y != 0.f) d_rr[row] = col + 1;
            if (a.z != 0.f) d_rr[row] = col + 2;
            if (a.w != 0.f) d_rr[row] = col + 3;
        }
        float4 s = Rs4[i];
        if (s.x != 0.f || s.y != 0.f || s.z != 0.f || s.w != 0.f) {
            int base = i << 2, row = base >> 11, col = base & 2047;
            if (s.x != 0.f) d_rs[row] = col;
            if (s.y != 0.f) d_rs[row] = col + 1;
            if (s.z != 0.f) d_rs[row] = col + 2;
            if (s.w != 0.f) d_rs[row] = col + 3;
        }
    }
}

// ---------------------------------------------------------------------------
// Build p_inputs [B,N,19]
// ---------------------------------------------------------------------------
__global__ void build_pinp_k(const float* __restrict__ state, const float* __restrict__ attrs,
                             const float* __restrict__ action, const float* __restrict__ pden,
                             const float* __restrict__ phys) {
    int i = blockIdx.x * blockDim.x + threadIdx.x;
    if (i >= Bn * NN) return;
    int b = i >> 11, n = i & 2047;
    float* o = d_pinp + i * 19;
    o[0] = attrs[i * 2 + 0];
    o[1] = attrs[i * 2 + 1];
    const float* st = state + (size_t)(b * 4) * NN * 3 + (size_t)n * 3;
    const int HS = NN * 3;
    float s0[3], s1v[3], s2v[3], s3[3];
#pragma unroll
    for (int c = 0; c < 3; c++) {
        s0[c] = st[c]; s1v[c] = st[HS + c]; s2v[c] = st[2 * HS + c]; s3[c] = st[3 * HS + c];
    }
#pragma unroll
    for (int c = 0; c < 3; c++) {
        o[2 + c] = s1v[c] - s0[c];
        o[5 + c] = s2v[c] - s1v[c];
        o[8 + c] = s3[c] - s2v[c];
        o[11 + c] = s3[c];
    }
    o[14] = (n < NP) ? phys[b] : 0.f;
#pragma unroll
    for (int c = 0; c < 3; c++) o[15 + c] = action[i * 3 + c];
    o[18] = (n < NP) ? pden[b] : 0.f;
}

// ---------------------------------------------------------------------------
// Build rel_inputs [B,n_rel,56]
// ---------------------------------------------------------------------------
__global__ void build_relinp_k(const float* __restrict__ attrs, const float* __restrict__ pinst) {
    int i = blockIdx.x * blockDim.x + threadIdx.x;
    if (i >= Bn * NREL) return;
    int b = i >> 13;
    int nr = d_rr[i], ns = d_rs[i];
    const float* pr = d_pinp + ((b << 11) + nr) * 19;
    const float* ps = d_pinp + ((b << 11) + ns) * 19;
    float* o = d_relinp + i * 56;
#pragma unroll
    for (int c = 0; c < 19; c++) { o[c] = pr[c]; o[19 + c] = ps[c]; }
    o[38] = attrs[((b << 11) + nr) * 2 + 0];
    o[39] = attrs[((b << 11) + nr) * 2 + 1];
    o[40] = attrs[((b << 11) + ns) * 2 + 0];
    o[41] = attrs[((b << 11) + ns) * 2 + 1];
    float gd = 0.f;
    bool ri = nr < NP, si = ns < NP;
    if (ri && si) {
        const float* gr = pinst + (b * NP + nr) * 8;
        const float* gs = pinst + (b * NP + ns) * 8;
#pragma unroll
        for (int j = 0; j < 8; j++) gd += fabsf(gr[j] - gs[j]);
    } else if (ri || si) {
        const float* g1 = pinst + (b * NP + (ri ? nr : ns)) * 8;
#pragma unroll
        for (int j = 0; j < 8; j++) gd += fabsf(g1[j]);
    }
    o[42] = gd;
#pragma unroll
    for (int c = 0; c < 12; c++) o[43 + c] = pr[2 + c] - ps[2 + c];
    o[55] = pr[18] - ps[18];
}

// ---------------------------------------------------------------------------
// Shared helpers for weight-resident kernels (256 threads, TR=16 rows/tile)
// ---------------------------------------------------------------------------
constexpr int TR = 16;   // rows per tile
constexpr int RPT = 8;   // rows per thread (TR/2; t>>7 selects half)

// Load W [K x 128] into paired smem layout sWp[(k>>1)*256 + col*2 + (k&1)],
// zero-padding rows K..Kp-1. Reads coalesced float4.
__device__ __forceinline__ void load_W_paired(const float* __restrict__ W, int K, int Kp,
                                              float* sWp, int t) {
    for (int i = t; i < Kp * 32; i += 256) {
        int k = i >> 5, c4 = i & 31;
        float4 v = make_float4(0.f, 0.f, 0.f, 0.f);
        if (k < K) v = reinterpret_cast<const float4*>(W + (size_t)k * 128)[c4];
        float* dst = sWp + (k >> 1) * 256 + (k & 1);
        dst[(4 * c4 + 0) * 2] = v.x;
        dst[(4 * c4 + 1) * 2] = v.y;
        dst[(4 * c4 + 2) * 2] = v.z;
        dst[(4 * c4 + 3) * 2] = v.w;
    }
}

// One layer: res[r] = dot(sIn[row0+r, :Kp], Wp[:, col]) + bias  (f32x2 inner)
// sIn rows padded to Kp floats (Kp multiple of 8, rows 16B aligned).
template <int Kp>
__device__ __forceinline__ void layer_f32x2(const float* __restrict__ sIn,
                                            const float* __restrict__ sWp,
                                            float biasv, int col, int rowL0,
                                            float* res) {
    ull acc[RPT];
#pragma unroll
    for (int r = 0; r < RPT; r++) acc[r] = 0ull;
    const ull* wp = reinterpret_cast<const ull*>(sWp) + col;
#pragma unroll 1
    for (int k = 0; k < Kp; k += 8) {
        const ull w0 = wp[((k >> 1) + 0) * 128];
        const ull w1 = wp[((k >> 1) + 1) * 128];
        const ull w2 = wp[((k >> 1) + 2) * 128];
        const ull w3 = wp[((k >> 1) + 3) * 128];
#pragma unroll
        for (int r = 0; r < RPT; r++) {
            const ulonglong2* ap =
                reinterpret_cast<const ulonglong2*>(sIn + (rowL0 + r) * Kp + k);
            ulonglong2 a01 = ap[0];
            ulonglong2 a23 = ap[1];
            fma2(acc[r], a01.x, w0);
            fma2(acc[r], a01.y, w1);
            fma2(acc[r], a23.x, w2);
            fma2(acc[r], a23.y, w3);
        }
    }
#pragma unroll
    for (int r = 0; r < RPT; r++) res[r] = unpack_sum(acc[r]) + biasv;
}

// ---------------------------------------------------------------------------
// Fused weight-resident MLP (NL layers, all ReLU): A[M,K0] -> out[M,128]
// Layer dims: K0->128, then 128->128 ... Weights resident in smem for all layers.
// ---------------------------------------------------------------------------
template <int K0, int K0P, int NL>
__global__ void __launch_bounds__(256) mlp_fused_k(const float* __restrict__ A, int M,
                                                   const float* __restrict__ W0, const float* __restrict__ b0,
                                                   const float* __restrict__ W1, const float* __restrict__ b1,
                                                   const float* __restrict__ W2, const float* __restrict__ b2,
                                                   float* __restrict__ out) {
    extern __shared__ float sm[];
    float* sW0 = sm;                          // K0P*128
    float* sW1 = sW0 + K0P * 128;             // 128*128
    float* sW2 = sW1 + (NL > 1 ? 16384 : 0);  // 128*128 (NL==3)
    float* sb  = sW2 + (NL > 2 ? 16384 : 0);  // NL*128
    float* sIn = sb + NL * 128;               // TR*K0P
    float* sH0 = sIn + TR * K0P;              // TR*128
    float* sH1 = sH0 + TR * 128;              // TR*128

    const int t = threadIdx.x;
    const int col = t & 127;
    const int rowL0 = (t >> 7) * RPT;

    load_W_paired(W0, K0, K0P, sW0, t);
    if (NL > 1) load_W_paired(W1, 128, 128, sW1, t);
    if (NL > 2) load_W_paired(W2, 128, 128, sW2, t);
    if (t < 128) {
        sb[t] = b0[t];
        if (NL > 1) sb[128 + t] = b1[t];
        if (NL > 2) sb[256 + t] = b2[t];
    }

    const int nTiles = M / TR;
    for (int tile = blockIdx.x; tile < nTiles; tile += gridDim.x) {
        const int row0 = tile * TR;
        __syncthreads();   // protect sIn/sH from previous iteration readers
        for (int i = t; i < TR * K0P; i += 256) {
            int r = i / K0P, k = i - r * K0P;
            sIn[i] = (k < K0) ? A[(size_t)(row0 + r) * K0 + k] : 0.f;
        }
        __syncthreads();

        float res[RPT];
        // layer 0
        layer_f32x2<K0P>(sIn, sW0, sb[col], col, rowL0, res);
        if (NL == 1) {
#pragma unroll
            for (int r = 0; r < RPT; r++)
                out[(size_t)(row0 + rowL0 + r) * 128 + col] = fmaxf(res[r], 0.f);
            continue;
        }
#pragma unroll
        for (int r = 0; r < RPT; r++) sH0[(rowL0 + r) * 128 + col] = fmaxf(res[r], 0.f);
        __syncthreads();
        // layer 1
        layer_f32x2<128>(sH0, sW1, sb[128 + col], col, rowL0, res);
        if (NL == 2) {
#pragma unroll
            for (int r = 0; r < RPT; r++)
                out[(size_t)(row0 + rowL0 + r) * 128 + col] = fmaxf(res[r], 0.f);
            continue;
        }
#pragma unroll
        for (int r = 0; r < RPT; r++) sH1[(rowL0 + r) * 128 + col] = fmaxf(res[r], 0.f);
        __syncthreads();
        // layer 2
        layer_f32x2<128>(sH1, sW2, sb[256 + col], col, rowL0, res);
#pragma unroll
        for (int r = 0; r < RPT; r++)
            out[(size_t)(row0 + rowL0 + r) * 128 + col] = fmaxf(res[r], 0.f);
    }
}

// ---------------------------------------------------------------------------
// Relation propagator: out = relu([re | eff[rr] | eff[rs]] @ W + b), K=384
// Weight-resident; gathered A staging.
// ---------------------------------------------------------------------------
__global__ void __launch_bounds__(256) relprop_k(const float* __restrict__ eff,
                                                 const float* __restrict__ W,
                                                 const float* __restrict__ bias) {
    extern __shared__ float sm[];
    float* sWp = sm;                 // 384*128
    float* sb  = sWp + 384 * 128;    // 128
    float* sIn = sb + 128;           // TR*384

    const int t = threadIdx.x;
    const int col = t & 127;
    const int rowL0 = (t >> 7) * RPT;

    load_W_paired(W, 384, 384, sWp, t);
    if (t < 128) sb[t] = bias[t];

    const int nTiles = (Bn * NREL) / TR;
    for (int tile = blockIdx.x; tile < nTiles; tile += gridDim.x) {
        const int row0 = tile * TR;
        __syncthreads();
        // stage gathered A: TR rows x 96 float4 (3 segments x 32)
        for (int i = t; i < TR * 96; i += 256) {
            int r = i / 96, f4 = i - r * 96;
            int row = row0 + r;
            int seg = f4 >> 5, off = f4 & 31;
            const float4* s4;
            if (seg == 0) {
                s4 = reinterpret_cast<const float4*>(d_re + (size_t)row * 128);
            } else {
                int b = row >> 13;
                int idx = (seg == 1) ? d_rr[row] : d_rs[row];
                s4 = reinterpret_cast<const float4*>(eff + (size_t)((b << 11) + idx) * 128);
            }
            reinterpret_cast<float4*>(sIn)[i] = s4[off];
        }
        __syncthreads();

        float res[RPT];
        layer_f32x2<384>(sIn, sWp, sb[col], col, rowL0, res);
#pragma unroll
        for (int r = 0; r < RPT; r++)
            d_s2[(size_t)(row0 + rowL0 + r) * 128 + col] = fmaxf(res[r], 0.f);
    }
}

// ---------------------------------------------------------------------------
// Particle propagator: out = relu([pe | agg] @ W + b + resid), K=256
// ---------------------------------------------------------------------------
__global__ void __launch_bounds__(256) partprop_k(const float* __restrict__ resid,
                                                  const float* __restrict__ W,
                                                  const float* __restrict__ bias) {
    extern __shared__ float sm[];
    float* sWp = sm;                 // 256*128
    float* sb  = sWp + 256 * 128;    // 128
    float* sIn = sb + 128;           // TR*256

    const int t = threadIdx.x;
    const int col = t & 127;
    const int rowL0 = (t >> 7) * RPT;

    load_W_paired(W, 256, 256, sWp, t);
    if (t < 128) sb[t] = bias[t];

    const int nTiles = (Bn * NN) / TR;
    for (int tile = blockIdx.x; tile < nTiles; tile += gridDim.x) {
        const int row0 = tile * TR;
        __syncthreads();
        for (int i = t; i < TR * 64; i += 256) {   // 64 float4 per row
            int r = i / 64, f4 = i - r * 64;
            int row = row0 + r;
            int seg = f4 >> 5, off = f4 & 31;
            const float* base = (seg == 0) ? d_pe : d_agg;
            reinterpret_cast<float4*>(sIn)[i] =
                reinterpret_cast<const float4*>(base + (size_t)row * 128)[off];
        }
        __syncthreads();

        float res[RPT];
        layer_f32x2<256>(sIn, sWp, sb[col], col, rowL0, res);
#pragma unroll
        for (int r = 0; r < RPT; r++) {
            const size_t o = (size_t)(row0 + rowL0 + r) * 128 + col;
            d_peff[o] = fmaxf(res[r] + resid[o], 0.f);
        }
    }
}

// ---------------------------------------------------------------------------
// Scatter-add: agg[b, rr[r], :] += effect_rel[r, :]
// ---------------------------------------------------------------------------
__global__ void zero_agg_k() {
    int i = blockIdx.x * blockDim.x + threadIdx.x;
    if (i < Bn * NN * NFD) d_agg[i] = 0.f;
}

__global__ void scatter_k() {
    int i = blockIdx.x * blockDim.x + threadIdx.x;  // Bn*NREL*128
    int rg = i >> 7, dcol = i & 127;
    int b = rg >> 13;
    int n = d_rr[rg];
    atomicAdd(&d_agg[((b << 11) + n) * 128 + dcol], d_s2[i]);
}

// ---------------------------------------------------------------------------
// Final head: motion = h @ W2[128,3] + b2, clip, add last state
// ---------------------------------------------------------------------------
__global__ void final_k(const float* __restrict__ state, const float* __restrict__ W2,
                        const float* __restrict__ b2, float* __restrict__ out) {
    int i = blockIdx.x * blockDim.x + threadIdx.x;
    if (i >= Bn * NP * 3) return;
    int j = i % 3;
    int p = (i / 3) % NP;
    int b = i / (NP * 3);
    const float* h = d_s1 + ((b << 11) + p) * 128;
    float acc = b2[j];
#pragma unroll 4
    for (int k = 0; k < 128; k++) acc = fmaf(h[k], W2[k * 3 + j], acc);
    acc = fminf(fmaxf(acc, -100.f), 100.f);
    out[i] = state[((size_t)(b * 4 + 3) * NN + p) * 3 + j] + acc;
}

// ---------------------------------------------------------------------------
// Host launch (kernel launches + capture-safe symbol/attr calls only)
// ---------------------------------------------------------------------------
static float* symaddr(const void* s) {
    void* p = nullptr;
    cudaGetSymbolAddress(&p, s);
    return (float*)p;
}

// smem sizes in bytes
#define SM_PE ((24 * 128 + 2 * 16384 + 3 * 128 + TR * 24 + 2 * TR * 128) * 4)
#define SM_RE ((56 * 128 + 2 * 16384 + 3 * 128 + TR * 56 + 2 * TR * 128) * 4)
#define SM_NP ((128 * 128 + 1 * 16384 + 2 * 128 + TR * 128 + 2 * TR * 128) * 4)
#define SM_RP ((384 * 128 + 128 + TR * 384) * 4)
#define SM_PP ((256 * 128 + 128 + TR * 256) * 4)

extern "C" void kernel_launch(void* const* d_in, const int* in_sizes, int n_in,
                              void* d_out, int out_size) {
    const float* state = (const float*)d_in[0];
    const float* attrs = (const float*)d_in[1];
    const float* Rr    = (const float*)d_in[2];
    const float* Rs    = (const float*)d_in[3];
    const float* pinst = (const float*)d_in[4];
    const float* action = (const float*)d_in[5];
    const float* pden  = (const float*)d_in[6];
    const float* phys  = (const float*)d_in[7];
    const float* peW0 = (const float*)d_in[8],  *peb0 = (const float*)d_in[9];
    const float* peW1 = (const float*)d_in[10], *peb1 = (const float*)d_in[11];
    const float* peW2 = (const float*)d_in[12], *peb2 = (const float*)d_in[13];
    const float* reW0 = (const float*)d_in[14], *reb0 = (const float*)d_in[15];
    const float* reW1 = (const float*)d_in[16], *reb1 = (const float*)d_in[17];
    const float* reW2 = (const float*)d_in[18], *reb2 = (const float*)d_in[19];
    const float* ppW  = (const float*)d_in[20], *ppb  = (const float*)d_in[21];
    const float* rpW  = (const float*)d_in[22], *rpb  = (const float*)d_in[23];
    const float* npW0 = (const float*)d_in[24], *npb0 = (const float*)d_in[25];
    const float* npW1 = (const float*)d_in[26], *npb1 = (const float*)d_in[27];
    const float* npW2 = (const float*)d_in[28], *npb2 = (const float*)d_in[29];
    float* out = (float*)d_out;

    float* pinp = symaddr(d_pinp);
    float* reli = symaddr(d_relinp);
    float* pe   = symaddr(d_pe);
    float* re   = symaddr(d_re);
    float* peff = symaddr(d_peff);
    float* s1   = symaddr(d_s1);

    // raise dynamic smem caps (idempotent, capture-safe host calls)
    cudaFuncSetAttribute(mlp_fused_k<19, 24, 3>, cudaFuncAttributeMaxDynamicSharedMemorySize, SM_PE);
    cudaFuncSetAttribute(mlp_fused_k<56, 56, 3>, cudaFuncAttributeMaxDynamicSharedMemorySize, SM_RE);
    cudaFuncSetAttribute(mlp_fused_k<128, 128, 2>, cudaFuncAttributeMaxDynamicSharedMemorySize, SM_NP);
    cudaFuncSetAttribute(relprop_k, cudaFuncAttributeMaxDynamicSharedMemorySize, SM_RP);
    cudaFuncSetAttribute(partprop_k, cudaFuncAttributeMaxDynamicSharedMemorySize, SM_PP);

    // 1. indices from one-hot
    extract_idx_k<<<8192, 256>>>((const float4*)Rr, (const float4*)Rs);

    // 2. node features
    build_pinp_k<<<(Bn * NN + 127) / 128, 128>>>(state, attrs, action, pden, phys);

    // 3. particle encoder (fused 3 layers): 19 -> 128 -> 128 -> 128
    mlp_fused_k<19, 24, 3><<<148, 256, SM_PE>>>(pinp, Bn * NN,
        peW0, peb0, peW1, peb1, peW2, peb2, pe);

    // 4. edge features + relation encoder (fused 3 layers): 56 -> 3x128
    build_relinp_k<<<(Bn * NREL + 127) / 128, 128>>>(attrs, pinst);
    mlp_fused_k<56, 56, 3><<<148, 256, SM_RE>>>(reli, Bn * NREL,
        reW0, reb0, reW1, reb1, reW2, reb2, re);

    // 5. 3 propagation steps
    for (int p = 0; p < 3; p++) {
        const float* src = (p == 0) ? pe : peff;
        relprop_k<<<148, 256, SM_RP>>>(src, rpW, rpb);
        zero_agg_k<<<(Bn * NN * NFD) / 256, 256>>>();
        scatter_k<<<Bn * NREL, 128>>>();
        partprop_k<<<148, 256, SM_PP>>>(src, ppW, ppb);
    }

    // 6. motion head (fused 2 layers) + final
    mlp_fused_k<128, 128, 2><<<148, 256, SM_NP>>>(peff, Bn * NN,
        npW0, npb0, npW1, npb1, nullptr, nullptr, s1);
    final_k<<<(Bn * NP * 3 + 127) / 128, 128>>>(state, npW2, npb2, out);
}